// round 15
// baseline (speedup 1.0000x reference)
#include <cuda_runtime.h>

// CustomRouterRouter — reference-rounding-matched (Eigen/NEON gemv realization).
// Thread = (row, e): all 4 NEON lanes in-thread via 2x FFMA2 + LDS.128 pairs.
//
// Numerics (LOCKED, rel_err 3.06e-5): per (row,e), 4 fp32 lane accumulators,
// lane j takes k ≡ j (mod 4), fused FMA, ascending k; predux (a0+a2)+(a1+a3);
// single-rounding epilogue (+b, den add, IEEE div, mul-then-add).
// f32x2 lanes are independent IEEE fp32 -> bit-identical to scalar fmaf;
// in-thread add.rn.f32x2(acc01, acc23) = (a0+a2, a1+a3) exactly, then lo+hi.
//
// Perf (model validated R9-R14: LSU/issue-op bound): per row-packet
// 1 x-LDS.128 + 1 w-LDS.128 + 2 FFMA2 = 8 issue slots (was 12). Warp =
// 16 rows x 2e; half-warp = 8 rows -> conflict-free LDS.128 (stride 68
// words, banks 4r+4p distinct; e is broadcast). W in persistent smem.

#define FT   0.5f
#define PKT  16            // float4 packets per stage per row
#define STG  3             // pipeline stages (wait_group 2)
#define RPB  16            // rows per block
#define THR  32            // 1 warp: 16 rows x 2 experts
#define WPAD 4100          // W row stride in floats (4096 + 4 bank shift)

typedef unsigned long long u64;

__device__ __forceinline__ void cp_async16(void* smem_dst, const void* gmem_src) {
    unsigned saddr = (unsigned)__cvta_generic_to_shared(smem_dst);
    asm volatile("cp.async.cg.shared.global [%0], [%1], 16;\n"
                 :: "r"(saddr), "l"(gmem_src));
}
__device__ __forceinline__ void cp_commit() {
    asm volatile("cp.async.commit_group;\n" ::: "memory");
}
__device__ __forceinline__ void cp_wait() {
    asm volatile("cp.async.wait_group %0;\n" :: "n"(STG - 1) : "memory");
}
__device__ __forceinline__ void ffma2(u64& acc, u64 x, u64 w) {
    asm("fma.rn.f32x2 %0, %1, %2, %3;" : "=l"(acc) : "l"(x), "l"(w), "l"(acc));
}

__global__ __launch_bounds__(THR) void router_lane_kernel(
    const float4* __restrict__ x4,
    const float*  __restrict__ weights,
    const float*  __restrict__ W,
    const float*  __restrict__ b,
    float*        __restrict__ out,
    int L, int Hv)
{
    // x: [stage][row][packet], +1 float4 row pad (68-word stride).
    // sw: plain W rows, stride 4100 floats (16B-aligned, +4 bank shift).
    __shared__ float4 sx[STG][RPB][PKT + 1];   // 13.1 KB
    __shared__ float  sw[2 * WPAD];            // 32.8 KB  (45.9 KB static)

    const int tid     = threadIdx.x;
    const int e       = tid & 1;           // expert
    const int rloc    = tid >> 1;          // 0..15 (block-local row)
    const int rowbase = blockIdx.x * RPB;
    const int row     = rowbase + rloc;
    const int H       = Hv * 4;

    // ── Prologue: copy W into smem (plain layout, padded rows). ──
    for (int k = tid * 4; k < H; k += THR * 4) {
        *reinterpret_cast<float4*>(&sw[k])        = *reinterpret_cast<const float4*>(W + k);
        *reinterpret_cast<float4*>(&sw[WPAD + k]) = *reinterpret_cast<const float4*>(W + H + k);
    }
    __syncwarp();

    const float4* __restrict__ xblk = x4 + (size_t)rowbase * Hv;

    // Stage issue: 16 rows x 16 packets = 256 float4, 8 per thread, coalesced.
    auto issue = [&](int s, int st) {
        const int gp = s * PKT;
        #pragma unroll
        for (int k = 0; k < 8; k++) {
            const int idx = tid + k * THR;   // 0..255
            const int r   = idx >> 4;        // 0..15
            const int p   = idx & 15;
            cp_async16(&sx[st][r][p], &xblk[(size_t)r * Hv + gp + p]);
        }
        cp_commit();
    };

    issue(0, 0);
    issue(1, 1);

    // Two f32x2 chains per thread: acc01 = lanes (j0,j1), acc23 = (j2,j3).
    u64 acc01 = 0ull, acc23 = 0ull;

    const int nstages = Hv / PKT;          // 64
    int stc = 0;                            // consume slot
    int stp = STG - 1;                      // produce slot

    #pragma unroll 1
    for (int s = 0; s < nstages; s++) {
        if (s + STG - 1 < nstages) issue(s + STG - 1, stp);
        else                       cp_commit();

        cp_wait();
        __syncwarp();

        const ulonglong2* xq =
            reinterpret_cast<const ulonglong2*>(&sx[stc][rloc][0]);
        const ulonglong2* wq =
            reinterpret_cast<const ulonglong2*>(&sw[e * WPAD + s * (PKT * 4)]);
        #pragma unroll
        for (int p = 0; p < PKT; p++) {
            const ulonglong2 xv = xq[p];    // LDS.128: (x4p,x4p+1 | x4p+2,x4p+3)
            const ulonglong2 wv = wq[p];    // LDS.128
            ffma2(acc01, xv.x, wv.x);
            ffma2(acc23, xv.y, wv.y);
        }
        __syncwarp();

        stc = (stc + 1 == STG) ? 0 : stc + 1;
        stp = (stp + 1 == STG) ? 0 : stp + 1;
    }

    // Predux in-thread, Eigen NEON order: (a0+a2, a1+a3), then lo+hi.
    u64 sum2;
    asm("add.rn.f32x2 %0, %1, %2;" : "=l"(sum2) : "l"(acc01), "l"(acc23));
    const float slo = __uint_as_float((unsigned)(sum2 & 0xffffffffull));
    const float shi = __uint_as_float((unsigned)(sum2 >> 32));
    const float A   = __fadd_rn(slo, shi);

    // lin_e = A_e + b_e (single rounding); den via e-partner (adjacent lane).
    const float lin   = __fadd_rn(A, __ldg(&b[e]));
    const float other = __shfl_xor_sync(0xffffffffu, lin, 1);
    const float den   = __fadd_rn((e == 0) ? lin : other,
                                  (e == 0) ? other : lin);
    const float l     = __fdiv_rn(lin, den);

    // hs = weights[row // (L/2)][0]; weights is (2,2) row-major.
    const float hs = __ldg(&weights[(row >= (L >> 1)) ? 2 : 0]);

    float rr_self, rr2;
    if (hs >= FT) {
        rr2     = __fdiv_rn(__fsub_rn(1.0f, hs), 1.0f - FT);
        rr_self = (e == 0) ? __fdiv_rn(__fsub_rn(hs, FT), 1.0f - FT) : 0.0f;
    } else {
        rr2     = __fdiv_rn(hs, FT);
        rr_self = (e == 0) ? 0.0f : __fdiv_rn(__fsub_rn(FT, hs), FT);
    }

    out[row * 2 + e] = __fadd_rn(rr_self, __fmul_rn(rr2, l));
}

extern "C" void kernel_launch(void* const* d_in, const int* in_sizes, int n_in,
                              void* d_out, int out_size) {
    const float* x       = (const float*)d_in[0];
    const float* weights = (const float*)d_in[1];
    const float* W       = (const float*)d_in[2];
    const float* b       = (const float*)d_in[3];
    float* out = (float*)d_out;

    const int E  = in_sizes[3];            // 2
    const int H  = in_sizes[2] / E;        // 4096
    const int L  = in_sizes[0] / H;        // 8192
    const int Hv = H / 4;                  // 1024

    const int blocks = L / RPB;            // 512

    router_lane_kernel<<<blocks, THR>>>((const float4*)x, weights, W, b,
                                        out, L, Hv);
}

// round 16
// speedup vs baseline: 1.0691x; 1.0691x over previous
#include <cuda_runtime.h>

// CustomRouterRouter — reference-rounding-matched (Eigen/NEON gemv realization).
// Thread = (row, e), 4 lanes in-thread via 2x FFMA2; 4-warp blocks spread all
// SMSPs; warp-private cp.async staging; persistent W in dynamic smem.
//
// Numerics (LOCKED, rel_err 3.06e-5): per (row,e), 4 fp32 lane accumulators,
// lane j takes k ≡ j (mod 4), fused FMA, ascending k; predux (a0+a2)+(a1+a3);
// single-rounding epilogue (+b, den add, IEEE div, mul-then-add).
// f32x2 lanes are independent IEEE fp32 -> bit-identical to scalar fmaf;
// in-thread add.rn.f32x2(acc01, acc23) = (a0+a2, a1+a3), then lo+hi.
//
// Perf: R15 showed the minimal-op mapping loses to SMSP starvation with
// 1-warp blocks (all warps -> SMSP 0). This round: THR=128 (one warp per
// SMSP), RPB=64, 128 blocks, STG=4, 102 KB dynamic smem, W copied once per
// block (4x less W L2 traffic than R15).

#define FT   0.5f
#define PKT  16            // float4 packets per stage per row
#define STG  4             // pipeline stages (wait_group 3)
#define RPB  64            // rows per block (16 per warp)
#define THR  128           // 4 warps
#define WPAD 4100          // W row stride in floats (4096 + 4 bank shift)

typedef unsigned long long u64;

#define SX_BYTES (STG * RPB * (PKT + 1) * 16)          // 69632
#define SMEM_TOTAL (SX_BYTES + 2 * WPAD * 4)           // 102432

__device__ __forceinline__ void cp_async16(void* smem_dst, const void* gmem_src) {
    unsigned saddr = (unsigned)__cvta_generic_to_shared(smem_dst);
    asm volatile("cp.async.cg.shared.global [%0], [%1], 16;\n"
                 :: "r"(saddr), "l"(gmem_src));
}
__device__ __forceinline__ void cp_commit() {
    asm volatile("cp.async.commit_group;\n" ::: "memory");
}
__device__ __forceinline__ void cp_wait() {
    asm volatile("cp.async.wait_group %0;\n" :: "n"(STG - 1) : "memory");
}
__device__ __forceinline__ void ffma2(u64& acc, u64 x, u64 w) {
    asm("fma.rn.f32x2 %0, %1, %2, %3;" : "=l"(acc) : "l"(x), "l"(w), "l"(acc));
}

__global__ __launch_bounds__(THR) void router_lane_kernel(
    const float4* __restrict__ x4,
    const float*  __restrict__ weights,
    const float*  __restrict__ W,
    const float*  __restrict__ b,
    float*        __restrict__ out,
    int L, int Hv)
{
    extern __shared__ char smem[];
    // x: [stage][row][PKT+1] float4 (68-word row stride -> conflict-free).
    float4 (*sx)[RPB][PKT + 1] = reinterpret_cast<float4 (*)[RPB][PKT + 1]>(smem);
    // sw: plain W rows, stride 4100 floats (+4 bank shift between e0/e1).
    float* sw = reinterpret_cast<float*>(smem + SX_BYTES);

    const int tid     = threadIdx.x;
    const int lane    = tid & 31;
    const int wid     = tid >> 5;          // warp 0..3 (one per SMSP)
    const int e       = lane & 1;          // expert
    const int wrloc   = lane >> 1;         // warp-local row 0..15
    const int rloc    = wid * 16 + wrloc;  // block-local row 0..63
    const int rowbase = blockIdx.x * RPB;
    const int row     = rowbase + rloc;
    const int H       = Hv * 4;

    // ── Prologue: copy W into smem once per block. ──
    for (int k = tid * 4; k < H; k += THR * 4) {
        *reinterpret_cast<float4*>(&sw[k])        = *reinterpret_cast<const float4*>(W + k);
        *reinterpret_cast<float4*>(&sw[WPAD + k]) = *reinterpret_cast<const float4*>(W + H + k);
    }
    __syncthreads();

    // ── Warp-private x staging: warp owns rows [wid*16, wid*16+16). ──
    const float4* __restrict__ xwarp = x4 + (size_t)(rowbase + wid * 16) * Hv;

    auto issue = [&](int s, int st) {
        const int gp = s * PKT;
        #pragma unroll
        for (int k = 0; k < 8; k++) {
            const int idx = lane + k * 32;   // 0..255
            const int r   = idx >> 4;        // 0..15
            const int p   = idx & 15;
            cp_async16(&sx[st][wid * 16 + r][p], &xwarp[(size_t)r * Hv + gp + p]);
        }
        cp_commit();
    };

    issue(0, 0);
    issue(1, 1);
    issue(2, 2);

    // Two f32x2 chains per thread: acc01 = lanes (j0,j1), acc23 = (j2,j3).
    u64 acc01 = 0ull, acc23 = 0ull;

    const int nstages = Hv / PKT;          // 64
    int stc = 0;                            // consume slot
    int stp = STG - 1;                      // produce slot

    #pragma unroll 1
    for (int s = 0; s < nstages; s++) {
        if (s + STG - 1 < nstages) issue(s + STG - 1, stp);
        else                       cp_commit();

        cp_wait();
        __syncwarp();

        const ulonglong2* xq =
            reinterpret_cast<const ulonglong2*>(&sx[stc][rloc][0]);
        const ulonglong2* wq =
            reinterpret_cast<const ulonglong2*>(&sw[e * WPAD + s * (PKT * 4)]);
        #pragma unroll
        for (int p = 0; p < PKT; p++) {
            const ulonglong2 xv = xq[p];    // LDS.128
            const ulonglong2 wv = wq[p];    // LDS.128 (broadcast)
            ffma2(acc01, xv.x, wv.x);
            ffma2(acc23, xv.y, wv.y);
        }
        __syncwarp();

        stc = (stc + 1 == STG) ? 0 : stc + 1;
        stp = (stp + 1 == STG) ? 0 : stp + 1;
    }

    // Predux in-thread, Eigen NEON order: (a0+a2, a1+a3), then lo+hi.
    u64 sum2;
    asm("add.rn.f32x2 %0, %1, %2;" : "=l"(sum2) : "l"(acc01), "l"(acc23));
    const float slo = __uint_as_float((unsigned)(sum2 & 0xffffffffull));
    const float shi = __uint_as_float((unsigned)(sum2 >> 32));
    const float A   = __fadd_rn(slo, shi);

    // lin_e = A_e + b_e (single rounding); den via e-partner (adjacent lane).
    const float lin   = __fadd_rn(A, __ldg(&b[e]));
    const float other = __shfl_xor_sync(0xffffffffu, lin, 1);
    const float den   = __fadd_rn((e == 0) ? lin : other,
                                  (e == 0) ? other : lin);
    const float l     = __fdiv_rn(lin, den);

    // hs = weights[row // (L/2)][0]; weights is (2,2) row-major.
    const float hs = __ldg(&weights[(row >= (L >> 1)) ? 2 : 0]);

    float rr_self, rr2;
    if (hs >= FT) {
        rr2     = __fdiv_rn(__fsub_rn(1.0f, hs), 1.0f - FT);
        rr_self = (e == 0) ? __fdiv_rn(__fsub_rn(hs, FT), 1.0f - FT) : 0.0f;
    } else {
        rr2     = __fdiv_rn(hs, FT);
        rr_self = (e == 0) ? 0.0f : __fdiv_rn(__fsub_rn(FT, hs), FT);
    }

    out[row * 2 + e] = __fadd_rn(rr_self, __fmul_rn(rr2, l));
}

extern "C" void kernel_launch(void* const* d_in, const int* in_sizes, int n_in,
                              void* d_out, int out_size) {
    const float* x       = (const float*)d_in[0];
    const float* weights = (const float*)d_in[1];
    const float* W       = (const float*)d_in[2];
    const float* b       = (const float*)d_in[3];
    float* out = (float*)d_out;

    const int E  = in_sizes[3];            // 2
    const int H  = in_sizes[2] / E;        // 4096
    const int L  = in_sizes[0] / H;        // 8192
    const int Hv = H / 4;                  // 1024

    static int smem_set = 0;
    if (!smem_set) {
        cudaFuncSetAttribute(router_lane_kernel,
                             cudaFuncAttributeMaxDynamicSharedMemorySize,
                             SMEM_TOTAL);
        smem_set = 1;
    }

    const int blocks = L / RPB;            // 128

    router_lane_kernel<<<blocks, THR, SMEM_TOTAL>>>(
        (const float4*)x, weights, W, b, out, L, Hv);
}